// round 4
// baseline (speedup 1.0000x reference)
#include <cuda_runtime.h>
#include <cstdint>

#define BATCH 64
#define TLEN  512
#define D     1024

// ---------------- scratch (device globals: no allocations allowed) ----------------
__device__ float g_ext[(size_t)BATCH * TLEN * D];   // 128 MB: input projections
__device__ float g_stateA[BATCH * D];
__device__ float g_stateB[BATCH * D];
__device__ unsigned g_bars[4 * 32];                  // per-m-group barrier counters, 128B apart

// ---------------- packed f32x2 helpers (sm_103a FFMA2 path) ----------------
static __device__ __forceinline__ unsigned long long pack_dup(float w) {
    unsigned long long r;
    asm("mov.b64 %0, {%1, %1};" : "=l"(r) : "f"(w));
    return r;
}
static __device__ __forceinline__ void fma2(unsigned long long& d,
                                            unsigned long long a,
                                            unsigned long long b) {
    asm("fma.rn.f32x2 %0, %1, %2, %0;" : "+l"(d) : "l"(a), "l"(b));
}
static __device__ __forceinline__ void unpack2(unsigned long long v, float& lo, float& hi) {
    asm("mov.b64 {%0, %1}, %2;" : "=f"(lo), "=f"(hi) : "l"(v));
}

// ---------------- trivial zero kernels ----------------
__global__ void zero4_kernel(float4* __restrict__ p, int n4) {
    int i = blockIdx.x * blockDim.x + threadIdx.x;
    if (i < n4) p[i] = make_float4(0.f, 0.f, 0.f, 0.f);
}
__global__ void zero_state_kernel() {
    int i = blockIdx.x * blockDim.x + threadIdx.x;
    if (i < BATCH * D) g_stateA[i] = 0.f;
    if (i < 4 * 32) g_bars[i] = 0u;
}

// ---------------- Phase A: ext[m][n] = sum_k x[m][k] * W_in[n][k] ----------------
// M=32768, N=1024, K=1024. BM=128, BN=64, BK=32, 256 threads, 8m x 4n per thread.
// Double-buffered smem (ping-pong), LDG for stage s^1 issued before compute on s.
#define BM 128
#define BN 64
#define BK 32
#define PADA 134
#define PADB 68
#define ASTRIDE (BK * PADA)
#define BSTRIDE (BK * PADB)
#define EXT_SMEM ((2 * ASTRIDE + 2 * BSTRIDE) * 4)   // 51712 B

__global__ __launch_bounds__(256) void ext_gemm_kernel(const float* __restrict__ X,
                                                       const float* __restrict__ Win) {
    extern __shared__ float esm[];
    float* As = esm;                       // 2 stages, As[k][m]
    float* Bs = esm + 2 * ASTRIDE;         // 2 stages, Bs[k][n]

    const int tid = threadIdx.x;
    const int Mb = blockIdx.y * BM;
    const int Nb = blockIdx.x * BN;
    const int ty = tid >> 4, tx = tid & 15;
    const int m0 = ty * 8, n0 = tx * 4;

    unsigned long long acc[4][4];
#pragma unroll
    for (int i = 0; i < 4; ++i)
#pragma unroll
        for (int j = 0; j < 4; ++j) acc[i][j] = 0ULL;

    const int ar = tid >> 3, ac = tid & 7;   // A loader: row ar(+g*32), 4k at ac*4
    const int br = tid >> 2, bc = tid & 3;   // B loader: row br, 4k at (bc+g*4)*4

    float4 ra[4], rb[2];

    // preload k-tile 0
#pragma unroll
    for (int g = 0; g < 4; ++g)
        ra[g] = *(const float4*)&X[(size_t)(Mb + ar + g * 32) * D + ac * 4];
#pragma unroll
    for (int g = 0; g < 2; ++g)
        rb[g] = *(const float4*)&Win[(size_t)(Nb + br) * D + (bc + g * 4) * 4];
    {
        float* A0 = As;
        float* B0 = Bs;
#pragma unroll
        for (int g = 0; g < 4; ++g) {
            const int m = ar + g * 32;
            A0[(ac * 4 + 0) * PADA + m] = ra[g].x;
            A0[(ac * 4 + 1) * PADA + m] = ra[g].y;
            A0[(ac * 4 + 2) * PADA + m] = ra[g].z;
            A0[(ac * 4 + 3) * PADA + m] = ra[g].w;
        }
#pragma unroll
        for (int g = 0; g < 2; ++g) {
            const int cc = bc + g * 4;
            B0[(cc * 4 + 0) * PADB + br] = rb[g].x;
            B0[(cc * 4 + 1) * PADB + br] = rb[g].y;
            B0[(cc * 4 + 2) * PADB + br] = rb[g].z;
            B0[(cc * 4 + 3) * PADB + br] = rb[g].w;
        }
    }
    __syncthreads();

    for (int kt = 0; kt < D / BK; ++kt) {
        const int s = kt & 1;
        const float* Ac = As + s * ASTRIDE;
        const float* Bc = Bs + s * BSTRIDE;

        if (kt < D / BK - 1) {
            const int k0 = (kt + 1) * BK;
#pragma unroll
            for (int g = 0; g < 4; ++g)
                ra[g] = *(const float4*)&X[(size_t)(Mb + ar + g * 32) * D + k0 + ac * 4];
#pragma unroll
            for (int g = 0; g < 2; ++g)
                rb[g] = *(const float4*)&Win[(size_t)(Nb + br) * D + k0 + (bc + g * 4) * 4];
        }

#pragma unroll
        for (int kk = 0; kk < BK; ++kk) {
            const float* asr = &Ac[kk * PADA + m0];
            unsigned long long a0 = *(const unsigned long long*)(asr + 0);
            unsigned long long a1 = *(const unsigned long long*)(asr + 2);
            unsigned long long a2 = *(const unsigned long long*)(asr + 4);
            unsigned long long a3 = *(const unsigned long long*)(asr + 6);
            float4 bv = *(const float4*)&Bc[kk * PADB + n0];
            unsigned long long b0 = pack_dup(bv.x);
            unsigned long long b1 = pack_dup(bv.y);
            unsigned long long b2 = pack_dup(bv.z);
            unsigned long long b3 = pack_dup(bv.w);
            fma2(acc[0][0], a0, b0); fma2(acc[0][1], a0, b1); fma2(acc[0][2], a0, b2); fma2(acc[0][3], a0, b3);
            fma2(acc[1][0], a1, b0); fma2(acc[1][1], a1, b1); fma2(acc[1][2], a1, b2); fma2(acc[1][3], a1, b3);
            fma2(acc[2][0], a2, b0); fma2(acc[2][1], a2, b1); fma2(acc[2][2], a2, b2); fma2(acc[2][3], a2, b3);
            fma2(acc[3][0], a3, b0); fma2(acc[3][1], a3, b1); fma2(acc[3][2], a3, b2); fma2(acc[3][3], a3, b3);
        }

        if (kt < D / BK - 1) {
            float* An = As + (s ^ 1) * ASTRIDE;
            float* Bn = Bs + (s ^ 1) * BSTRIDE;
#pragma unroll
            for (int g = 0; g < 4; ++g) {
                const int m = ar + g * 32;
                An[(ac * 4 + 0) * PADA + m] = ra[g].x;
                An[(ac * 4 + 1) * PADA + m] = ra[g].y;
                An[(ac * 4 + 2) * PADA + m] = ra[g].z;
                An[(ac * 4 + 3) * PADA + m] = ra[g].w;
            }
#pragma unroll
            for (int g = 0; g < 2; ++g) {
                const int cc = bc + g * 4;
                Bn[(cc * 4 + 0) * PADB + br] = rb[g].x;
                Bn[(cc * 4 + 1) * PADB + br] = rb[g].y;
                Bn[(cc * 4 + 2) * PADB + br] = rb[g].z;
                Bn[(cc * 4 + 3) * PADB + br] = rb[g].w;
            }
        }
        __syncthreads();
    }

#pragma unroll
    for (int i = 0; i < 4; ++i) {
        float lo[4], hi[4];
#pragma unroll
        for (int j = 0; j < 4; ++j) unpack2(acc[i][j], lo[j], hi[j]);
        const int m = Mb + m0 + 2 * i;
        *(float4*)&g_ext[(size_t)m * D + Nb + n0]       = make_float4(lo[0], lo[1], lo[2], lo[3]);
        *(float4*)&g_ext[(size_t)(m + 1) * D + Nb + n0] = make_float4(hi[0], hi[1], hi[2], hi[3]);
    }
}

// ---------------- Phase B: persistent recurrence kernel ----------------
// Grid (32 n-tiles, 4 m-groups) = 128 CTAs, 512 threads, 1 CTA/SM. W_rec slice
// resident in smem. Per step: K processed in 4 chunks of 256 — LDG chunk c+1
// issued while computing chunk c. 16 warps = 16 k-slices per chunk (16 k each),
// 4m x 4n per thread with k-pair-packed FFMA2, smem reduction, per-m-group
// 32-CTA spin barrier (groups are independent in batch).
#define NTILE 32
#define MTILE 16
#define ROWST 1028
#define PERS_SMEM ((NTILE + MTILE) * ROWST * 4)   // 197376 B

__global__ __launch_bounds__(512, 1) void rnn_persistent(const float* __restrict__ Wr) {
    extern __shared__ float sm[];
    float* Wsm = sm;                       // [32][ROWST]
    float* sT  = sm + NTILE * ROWST;       // [16][ROWST]
    unsigned long long* red = (unsigned long long*)sT;   // aliased: [16][512]

    const int tid = threadIdx.x;
    const int Nb = blockIdx.x * NTILE;
    const int Mb = blockIdx.y * MTILE;
    unsigned* bar = &g_bars[blockIdx.y * 32];

    // ---- load W slice once (resident for all steps) ----
    {
        const int n = tid >> 4, c = tid & 15;
        const float* wrow = Wr + (size_t)(Nb + n) * D;
        float* dst = Wsm + n * ROWST;
#pragma unroll
        for (int j = 0; j < 16; ++j) {
            const int q = c + j * 16;
            *(float4*)&dst[q * 4] = *(const float4*)&wrow[q * 4];
        }
    }

    // compute decomposition: warp = k-slice (16 k per chunk)
    const int kg = tid >> 5;                // 0..15
    const int lane = tid & 31;
    const int mi = lane & 3;                // m rows: mi, mi+4, mi+8, mi+12
    const int ni = lane >> 2;               // n rows: ni, ni+8, ni+16, ni+24

    // load/reduce decomposition
    const int lm = tid >> 5;                // 0..15 (row)
    const int lc = tid & 31;                // 0..31 (float4 col within chunk: lc, lc+32)

    for (int t = 0; t < TLEN; ++t) {
        const float* sin = (t & 1) ? g_stateB : g_stateA;
        float* sout      = (t & 1) ? g_stateA : g_stateB;

        const float4* srow = (const float4*)(sin + (size_t)(Mb + lm) * D);
        const float4* erow = (const float4*)(g_ext + (size_t)(Mb + lm) * (TLEN * D) + (size_t)t * D);
        float* drow = sT + lm * ROWST;

        // ---- chunk 0 load (64 float4 per row; this thread: 2) ----
        {
#pragma unroll
            for (int j = 0; j < 2; ++j) {
                const int q = lc + j * 32;
                float4 a = __ldcg(srow + q);
                float4 b = __ldg(erow + q);
                *(float4*)&drow[q * 4] = make_float4(a.x + b.x, a.y + b.y, a.z + b.z, a.w + b.w);
            }
        }
        __syncthreads();

        unsigned long long acc[16];
#pragma unroll
        for (int i = 0; i < 16; ++i) acc[i] = 0ULL;

#pragma unroll
        for (int c = 0; c < 4; ++c) {
            // issue loads for next chunk early (LDG latency hidden by compute)
            float4 nx[2];
            if (c < 3) {
#pragma unroll
                for (int j = 0; j < 2; ++j) {
                    const int q = (c + 1) * 64 + lc + j * 32;
                    float4 a = __ldcg(srow + q);
                    float4 b = __ldg(erow + q);
                    nx[j] = make_float4(a.x + b.x, a.y + b.y, a.z + b.z, a.w + b.w);
                }
            }

            // compute this chunk: warp kg covers k in [c*256 + kg*16, +16)
            const float* aB = sT + (size_t)mi * ROWST + c * 256 + kg * 16;
            const float* bB = Wsm + (size_t)ni * ROWST + c * 256 + kg * 16;
#pragma unroll
            for (int it = 0; it < 4; ++it) {
                const int k = it * 4;
                ulonglong2 av[4], bv[4];
#pragma unroll
                for (int r = 0; r < 4; ++r)
                    av[r] = *(const ulonglong2*)(aB + r * (4 * ROWST) + k);
#pragma unroll
                for (int q = 0; q < 4; ++q)
                    bv[q] = *(const ulonglong2*)(bB + q * (8 * ROWST) + k);
#pragma unroll
                for (int r = 0; r < 4; ++r)
#pragma unroll
                    for (int q = 0; q < 4; ++q) {
                        fma2(acc[r * 4 + q], av[r].x, bv[q].x);
                        fma2(acc[r * 4 + q], av[r].y, bv[q].y);
                    }
            }

            if (c < 3) {
#pragma unroll
                for (int j = 0; j < 2; ++j) {
                    const int q = (c + 1) * 64 + lc + j * 32;
                    *(float4*)&drow[q * 4] = nx[j];
                }
            }
            __syncthreads();
        }

        // ---- store k-slice partials (swizzled; red aliases sT, safe after sync) ----
#pragma unroll
        for (int r = 0; r < 4; ++r)
#pragma unroll
            for (int q = 0; q < 4; ++q) {
                const int m = mi + 4 * r, n = ni + 8 * q;
                red[kg * 512 + m * 32 + (n ^ (mi << 2))] = acc[r * 4 + q];
            }
        __syncthreads();

        // ---- reduce 16 partials, ReLU, write new state ----
        {
            const int m = lm, n = lc;
            const int idx = m * 32 + (n ^ ((m & 3) << 2));
            float lo = 0.f, hi = 0.f;
#pragma unroll
            for (int g = 0; g < 16; ++g) {
                float2 v = *(const float2*)&red[g * 512 + idx];
                lo += v.x; hi += v.y;
            }
            sout[(size_t)(Mb + m) * D + (Nb + n)] = fmaxf(lo + hi, 0.f);
        }

        // ---- per-m-group barrier (32 CTAs; groups independent in batch) ----
        __syncthreads();
        if (tid == 0) {
            __threadfence();                         // release state writes
            atomicAdd(bar, 1u);
            const unsigned target = 32u * (unsigned)(t + 1);
            unsigned v;
            do {
                asm volatile("ld.acquire.gpu.u32 %0, [%1];" : "=r"(v) : "l"(bar));
            } while (v < target);
        }
        __syncthreads();
    }
}

// ---------------- final: out[:,0,:] = final state ----------------
__global__ void final_copy_kernel(float* __restrict__ out) {
    const int i = blockIdx.x * blockDim.x + threadIdx.x;   // < 65536
    const int b = i >> 10, o = i & 1023;
    out[(size_t)b * (TLEN * D) + o] = g_stateA[i];
}

// ---------------- launch ----------------
extern "C" void kernel_launch(void* const* d_in, const int* in_sizes, int n_in,
                              void* d_out, int out_size) {
    const float* x     = (const float*)d_in[0];
    const float* W_in  = (const float*)d_in[1];
    const float* W_rec = (const float*)d_in[2];
    float* out = (float*)d_out;

    cudaFuncSetAttribute(rnn_persistent, cudaFuncAttributeMaxDynamicSharedMemorySize, PERS_SMEM);
    cudaFuncSetAttribute(ext_gemm_kernel, cudaFuncAttributeMaxDynamicSharedMemorySize, EXT_SMEM);

    // zero output (poisoned by harness), initial state, barrier counters
    zero4_kernel<<<(BATCH * TLEN * D / 4 + 255) / 256, 256>>>((float4*)out, BATCH * TLEN * D / 4);
    zero_state_kernel<<<(BATCH * D + 255) / 256, 256>>>();

    // Phase A: input projections for all timesteps
    ext_gemm_kernel<<<dim3(D / BN, (BATCH * TLEN) / BM), 256, EXT_SMEM>>>(x, W_in);

    // Phase B: full recurrence in one persistent kernel
    rnn_persistent<<<dim3(D / NTILE, BATCH / MTILE), 512, PERS_SMEM>>>(W_rec);

    // write final state into out[:,0,:]
    final_copy_kernel<<<(BATCH * D) / 256, 256>>>(out);
}